// round 13
// baseline (speedup 1.0000x reference)
#include <cuda_runtime.h>
#include <math.h>

#define NCTA 128
#define NTHR 256
#define Bb 256
#define Ss 512
#define Ii 256
#define Hh 512
#define BBd 256
#define Oo 128

// shared memory layout (floats)
#define P1   772
#define PB   260
#define PA1  132
#define PAH  68

#define OFF_W1  0
#define SZ_W1   (16 * P1)          // 12352
#define OFF_WB  (OFF_W1 + SZ_W1)
#define SZ_WB   (48 * PB)          // 12480
#define OFF_WH  (OFF_WB + SZ_WB)
#define SZ_WH   (64 * PB)          // 16640
#define OFF_ACT (OFF_WH + SZ_WH)
#define SZ_ACTBUF 4352
#define SMEM_FLOATS (OFF_ACT + 3 * SZ_ACTBUF)   // 54528
#define SMEM_BYTES  (SMEM_FLOATS * 4)           // 218112

typedef unsigned long long u64;

// ---------------- device scratch ----------
__device__ float g_h[Bb * Hh];
__device__ float g_zA[Bb * BBd];
__device__ float g_zB[Bb * BBd];
__device__ int   g_abort = 0;

struct __align__(128) Bar { unsigned count; unsigned gen; unsigned pad[30]; };
__device__ Bar g_bar16[8];
__device__ Bar g_bar32[4];

// ---------------- group barrier: acq/rel atomics, no MEMBAR ----------------
// Same counter+generation topology proven in R3/R4/R8/R11; only the memory
// ordering primitives changed (release-arrive / acquire-spin instead of
// __threadfence pairs). Release on the arrive orders this CTA's prior global
// stores AND the preceding gen read; acq_rel exch on the reset makes the last
// CTA a synchronization hub; acquire on the spin completes the chain.
__device__ __forceinline__ void group_barrier(Bar* b, unsigned nctas) {
    __syncthreads();
    if (threadIdx.x == 0) {
        unsigned* pcount = &b->count;
        unsigned* pgen   = &b->gen;
        unsigned gen;
        asm volatile("ld.relaxed.gpu.u32 %0, [%1];" : "=r"(gen) : "l"(pgen));
        unsigned rank;
        asm volatile("atom.add.release.gpu.u32 %0, [%1], 1;"
                     : "=r"(rank) : "l"(pcount) : "memory");
        if (rank == nctas - 1) {
            unsigned dummy;
            asm volatile("atom.exch.acq_rel.gpu.b32 %0, [%1], 0;"
                         : "=r"(dummy) : "l"(pcount) : "memory");
            (void)dummy;
            asm volatile("red.add.release.gpu.u32 [%0], 1;"
                         :: "l"(pgen) : "memory");
        } else {
            long long t0 = clock64();
            unsigned it = 0;
            for (;;) {
                unsigned v;
                asm volatile("ld.acquire.gpu.u32 %0, [%1];"
                             : "=r"(v) : "l"(pgen) : "memory");
                if (v != gen) break;
                if (((++it) & 1023u) == 0u) {
                    if (*(volatile int*)&g_abort) break;
                    if (clock64() - t0 > 2000000000LL) { atomicExch(&g_abort, 1); break; }
                }
            }
        }
    }
    __syncthreads();
}

// ---------------- packed f32x2 FMA -----------------------------------------
__device__ __forceinline__ u64 ffma2(u64 a, u64 b, u64 c) {
    u64 d;
    asm("fma.rn.f32x2 %0, %1, %2, %3;" : "=l"(d) : "l"(a), "l"(b), "l"(c));
    return d;
}
__device__ __forceinline__ float sum2(u64 v) {
    union { u64 u; float2 f; } cv; cv.u = v;
    return cv.f.x + cv.f.y;
}

// ---------------- cp.async ----------------
__device__ __forceinline__ void cp16(float* sdst, const float* gsrc) {
    unsigned saddr = (unsigned)__cvta_generic_to_shared(sdst);
    asm volatile("cp.async.cg.shared.global [%0], [%1], 16;" :: "r"(saddr), "l"(gsrc));
}
__device__ __forceinline__ void cp_commit() { asm volatile("cp.async.commit_group;"); }
__device__ __forceinline__ void cp_wait0()  { asm volatile("cp.async.wait_group 0;"); }
__device__ __forceinline__ void cp_wait1()  { asm volatile("cp.async.wait_group 1;"); }

__device__ __forceinline__ void load_rows32(float* sdst, const float* gbase, int gstride) {
    int tid = threadIdx.x;
#pragma unroll
    for (int i = 0; i < 4; i++) {
        int e = tid + i * 256;
        int r = e >> 5, v = e & 31;
        cp16(sdst + r * PA1 + v * 4, gbase + (size_t)r * gstride + v * 4);
    }
}
__device__ __forceinline__ void load_rows64(float* sdst, const float* gbase, int gstride) {
    int tid = threadIdx.x;
#pragma unroll
    for (int i = 0; i < 4; i++) {
        int e = tid + i * 256;
        int r = e >> 4, v = e & 15;
        cp16(sdst + r * PAH + v * 4, gbase + (size_t)r * gstride + v * 4);
    }
}

// 32x16 tile MAC over one 128-K chunk (2 rows/thread, 4 packed chains)
__device__ __forceinline__ void mac32x16(const float* sA, const float* wrow,
                                         u64& p0a, u64& p0b, u64& p1a, u64& p1b, int mg) {
    const ulonglong2* a0 = (const ulonglong2*)(sA + (mg * 2) * PA1);
    const ulonglong2* a1 = (const ulonglong2*)(sA + (mg * 2 + 1) * PA1);
    const ulonglong2* w4 = (const ulonglong2*)wrow;
#pragma unroll
    for (int q = 0; q < 32; q++) {
        ulonglong2 w  = w4[q];
        ulonglong2 x0 = a0[q];
        ulonglong2 x1 = a1[q];
        p0a = ffma2(x0.x, w.x, p0a);
        p0b = ffma2(x0.y, w.y, p0b);
        p1a = ffma2(x1.x, w.x, p1a);
        p1b = ffma2(x1.y, w.y, p1b);
    }
}

// heads: 4 rows x 4 mats over one 64-K chunk (16 packed chains)
__device__ __forceinline__ void mac_heads(const float* sA, const float* wbase,
                                          int mg, int ng, u64 acc[4][4]) {
    const ulonglong2* a0 = (const ulonglong2*)(sA + (mg * 4 + 0) * PAH);
    const ulonglong2* a1 = (const ulonglong2*)(sA + (mg * 4 + 1) * PAH);
    const ulonglong2* a2 = (const ulonglong2*)(sA + (mg * 4 + 2) * PAH);
    const ulonglong2* a3 = (const ulonglong2*)(sA + (mg * 4 + 3) * PAH);
    const ulonglong2* w0 = (const ulonglong2*)(wbase + (0 * 16 + ng) * PB);
    const ulonglong2* w1 = (const ulonglong2*)(wbase + (1 * 16 + ng) * PB);
    const ulonglong2* w2 = (const ulonglong2*)(wbase + (2 * 16 + ng) * PB);
    const ulonglong2* w3 = (const ulonglong2*)(wbase + (3 * 16 + ng) * PB);
#pragma unroll
    for (int q = 0; q < 16; q++) {
        ulonglong2 wv0 = w0[q], wv1 = w1[q], wv2 = w2[q], wv3 = w3[q];
        ulonglong2 av;
        av = a0[q];
        acc[0][0] = ffma2(av.x, wv0.x, acc[0][0]); acc[0][0] = ffma2(av.y, wv0.y, acc[0][0]);
        acc[0][1] = ffma2(av.x, wv1.x, acc[0][1]); acc[0][1] = ffma2(av.y, wv1.y, acc[0][1]);
        acc[0][2] = ffma2(av.x, wv2.x, acc[0][2]); acc[0][2] = ffma2(av.y, wv2.y, acc[0][2]);
        acc[0][3] = ffma2(av.x, wv3.x, acc[0][3]); acc[0][3] = ffma2(av.y, wv3.y, acc[0][3]);
        av = a1[q];
        acc[1][0] = ffma2(av.x, wv0.x, acc[1][0]); acc[1][0] = ffma2(av.y, wv0.y, acc[1][0]);
        acc[1][1] = ffma2(av.x, wv1.x, acc[1][1]); acc[1][1] = ffma2(av.y, wv1.y, acc[1][1]);
        acc[1][2] = ffma2(av.x, wv2.x, acc[1][2]); acc[1][2] = ffma2(av.y, wv2.y, acc[1][2]);
        acc[1][3] = ffma2(av.x, wv3.x, acc[1][3]); acc[1][3] = ffma2(av.y, wv3.y, acc[1][3]);
        av = a2[q];
        acc[2][0] = ffma2(av.x, wv0.x, acc[2][0]); acc[2][0] = ffma2(av.y, wv0.y, acc[2][0]);
        acc[2][1] = ffma2(av.x, wv1.x, acc[2][1]); acc[2][1] = ffma2(av.y, wv1.y, acc[2][1]);
        acc[2][2] = ffma2(av.x, wv2.x, acc[2][2]); acc[2][2] = ffma2(av.y, wv2.y, acc[2][2]);
        acc[2][3] = ffma2(av.x, wv3.x, acc[2][3]); acc[2][3] = ffma2(av.y, wv3.y, acc[2][3]);
        av = a3[q];
        acc[3][0] = ffma2(av.x, wv0.x, acc[3][0]); acc[3][0] = ffma2(av.y, wv0.y, acc[3][0]);
        acc[3][1] = ffma2(av.x, wv1.x, acc[3][1]); acc[3][1] = ffma2(av.y, wv1.y, acc[3][1]);
        acc[3][2] = ffma2(av.x, wv2.x, acc[3][2]); acc[3][2] = ffma2(av.y, wv2.y, acc[3][2]);
        acc[3][3] = ffma2(av.x, wv3.x, acc[3][3]); acc[3][3] = ffma2(av.y, wv3.y, acc[3][3]);
    }
}

__global__ void __launch_bounds__(NTHR, 1)
lnn_kernel(const float* __restrict__ x,     const float* __restrict__ ts,
           const float* __restrict__ Wb0,   const float* __restrict__ bb0,
           const float* __restrict__ Wbs,   const float* __restrict__ bbs,
           const float* __restrict__ W_ff1, const float* __restrict__ b_ff1,
           const float* __restrict__ W_ff2, const float* __restrict__ b_ff2,
           const float* __restrict__ W_ta,  const float* __restrict__ b_ta,
           const float* __restrict__ W_tb,  const float* __restrict__ b_tb,
           const float* __restrict__ W_out, const float* __restrict__ b_out,
           float* __restrict__ out) {
    extern __shared__ float smf[];
    const int tid = threadIdx.x;
    const int g   = blockIdx.x;
    const int n   = tid & 15;
    const int mg  = tid >> 4;     // 0..15
    const int m1  = g >> 4;
    const int n1  = g & 15;
    const int mh  = g >> 5;
    const int jh  = g & 31;

    Bar* barS = &g_bar16[m1];
    Bar* barH = &g_bar32[mh];

    if (tid == 0) *(volatile int*)&g_abort = 0;

    // ---- one-time weight loads (transposed, k contiguous) ----
    for (int e = tid; e < 16 * 768; e += NTHR) {
        int nn = e / 768, k = e % 768;
        smf[OFF_W1 + nn * P1 + k] = Wb0[k * BBd + n1 * 16 + nn];
    }
    for (int e = tid; e < 3 * 16 * 256; e += NTHR) {
        int l = e / (16 * 256);
        int rr = e % (16 * 256);
        int nn = rr / 256, k = rr % 256;
        smf[OFF_WB + (l * 16 + nn) * PB + k] = Wbs[(l * BBd + k) * BBd + n1 * 16 + nn];
    }
    for (int e = tid; e < 64 * 256; e += NTHR) {
        int rr = e / 256, k = e % 256;
        int hh = rr / 16, ng = rr % 16;
        const float* Wsrc = (hh == 0) ? W_ff1 : (hh == 1) ? W_ff2 : (hh == 2) ? W_ta : W_tb;
        smf[OFF_WH + rr * PB + k] = Wsrc[k * Hh + jh * 16 + ng];
    }
    float bz0   = bb0[n1 * 16 + n];
    float bb_l0 = bbs[0 * BBd + n1 * 16 + n];
    float bb_l1 = bbs[1 * BBd + n1 * 16 + n];
    float bb_l2 = bbs[2 * BBd + n1 * 16 + n];
    float bf1   = b_ff1[jh * 16 + n];
    float bf2   = b_ff2[jh * 16 + n];
    float bta   = b_ta [jh * 16 + n];
    float btb   = b_tb [jh * 16 + n];

    // zero h stripe (deterministic per replay)
    for (int e = tid; e < 1024; e += NTHR) g_h[g * 1024 + e] = 0.0f;
    __syncthreads();
    group_barrier(barH, 32);

    float* B0 = smf + OFF_ACT;
    float* B1 = B0 + SZ_ACTBUF;
    float* B2 = B1 + SZ_ACTBUF;

    const int rowPair = m1 * 32 + mg * 2;
    const int jS  = n1 * 16 + n;
    const int jHd = jh * 16 + n;
    const float* w1base = smf + OFF_W1 + n * P1;

    // stage1 accumulators carry across barriers (x-part precomputed)
    u64 p0a = 0, p0b = 0, p1a = 0, p1b = 0;
    {   // x-part for t = 0
        const float* xrb = x + ((size_t)(m1 * 32) * Ss + 0) * Ii;
        load_rows32(B0, xrb,       Ss * Ii); cp_commit();
        load_rows32(B1, xrb + 128, Ss * Ii); cp_commit();
        cp_wait1(); __syncthreads(); mac32x16(B0, w1base + 0,   p0a, p0b, p1a, p1b, mg);
        cp_wait0(); __syncthreads(); mac32x16(B1, w1base + 128, p0a, p0b, p1a, p1b, mg);
    }

    for (int t = 0; t < Ss; t++) {
        if (*(volatile int*)&g_abort) break;

        // ===== stage 1 h-part (h(t) sealed by barH of prev step) =====
        {
            const float* hb = g_h + (size_t)(m1 * 32) * Hh;
            load_rows32(B0, hb,       Hh); cp_commit();
            load_rows32(B1, hb + 128, Hh); cp_commit();
            // c0: B0 ready
            cp_wait1(); __syncthreads();
            load_rows32(B2, hb + 256, Hh); cp_commit();
            mac32x16(B0, w1base + 256, p0a, p0b, p1a, p1b, mg);
            // c1: B1 ready
            cp_wait1(); __syncthreads();
            load_rows32(B0, hb + 384, Hh); cp_commit();
            mac32x16(B1, w1base + 384, p0a, p0b, p1a, p1b, mg);
            // c2: B2 ready
            cp_wait1(); __syncthreads();
            mac32x16(B2, w1base + 512, p0a, p0b, p1a, p1b, mg);
            // c3: B0 ready
            cp_wait0(); __syncthreads();
            mac32x16(B0, w1base + 640, p0a, p0b, p1a, p1b, mg);

            g_zA[rowPair * BBd + jS]       = tanhf(sum2(p0a) + sum2(p0b) + bz0);
            g_zA[(rowPair + 1) * BBd + jS] = tanhf(sum2(p1a) + sum2(p1b) + bz0);
        }
        group_barrier(barS, 16);

        // ===== backbone x3 =====
#pragma unroll
        for (int l = 0; l < 3; l++) {
            const float* zin = (l == 1) ? g_zB : g_zA;
            float*       zot = (l == 1) ? g_zA : g_zB;
            u64 q0a = 0, q0b = 0, q1a = 0, q1b = 0;
            const float* zb = zin + (size_t)(m1 * 32) * BBd;
            load_rows32(B0, zb,       BBd); cp_commit();
            load_rows32(B1, zb + 128, BBd); cp_commit();
            const float* wb = smf + OFF_WB + (l * 16 + n) * PB;
            cp_wait1(); __syncthreads(); mac32x16(B0, wb,       q0a, q0b, q1a, q1b, mg);
            cp_wait0(); __syncthreads(); mac32x16(B1, wb + 128, q0a, q0b, q1a, q1b, mg);
            float bl = (l == 0) ? bb_l0 : (l == 1) ? bb_l1 : bb_l2;
            zot[rowPair * BBd + jS]       = tanhf(sum2(q0a) + sum2(q0b) + bl);
            zot[(rowPair + 1) * BBd + jS] = tanhf(sum2(q1a) + sum2(q1b) + bl);
            if (l < 2) group_barrier(barS, 16);
            else       group_barrier(barH, 32);
        }

        // ===== heads: ff1/ff2/ta/tb + gate -> new h =====
        {
            u64 acc[4][4];
#pragma unroll
            for (int i = 0; i < 4; i++)
#pragma unroll
                for (int hh = 0; hh < 4; hh++) acc[i][hh] = 0;

            const float* zb = g_zB + (size_t)(mh * 64) * BBd;
            load_rows64(B0, zb,       BBd); cp_commit();
            load_rows64(B1, zb + 64,  BBd); cp_commit();
            // c0
            cp_wait1(); __syncthreads();
            load_rows64(B2, zb + 128, BBd); cp_commit();
            mac_heads(B0, smf + OFF_WH + 0 * 64, mg, n, acc);
            // c1
            cp_wait1(); __syncthreads();
            load_rows64(B0, zb + 192, BBd); cp_commit();
            mac_heads(B1, smf + OFF_WH + 1 * 64, mg, n, acc);
            // c2
            cp_wait1(); __syncthreads();
            mac_heads(B2, smf + OFF_WH + 2 * 64, mg, n, acc);
            // c3
            cp_wait0(); __syncthreads();
            mac_heads(B0, smf + OFF_WH + 3 * 64, mg, n, acc);

#pragma unroll
            for (int i = 0; i < 4; i++) {
                int b = mh * 64 + mg * 4 + i;
                float tst = ts[(size_t)b * Ss + t];
                float f1  = tanhf(sum2(acc[i][0]) + bf1);
                float f2  = tanhf(sum2(acc[i][1]) + bf2);
                float ta_ = sum2(acc[i][2]) + bta;
                float tb_ = sum2(acc[i][3]) + btb;
                float ti  = 1.0f / (1.0f + __expf(-(ta_ * tst + tb_)));
                g_h[b * Hh + jHd] = f1 + ti * (f2 - f1);
            }
        }
        group_barrier(barH, 32);

        // ===== overlap: x-part of stage1 for t+1 (no h dependency) =====
        p0a = 0; p0b = 0; p1a = 0; p1b = 0;
        if (t + 1 < Ss) {
            const float* xrb = x + ((size_t)(m1 * 32) * Ss + (t + 1)) * Ii;
            load_rows32(B0, xrb,       Ss * Ii); cp_commit();
            load_rows32(B1, xrb + 128, Ss * Ii); cp_commit();
            cp_wait1(); __syncthreads(); mac32x16(B0, w1base + 0,   p0a, p0b, p1a, p1b, mg);
            cp_wait0(); __syncthreads(); mac32x16(B1, w1base + 128, p0a, p0b, p1a, p1b, mg);
        }
    }

    // ===== final: out = h_last @ W_out + b_out =====
    {
        int mo = g >> 2, no = g & 3;
        int m  = mo * 8 + (tid >> 5);
        int nn = no * 32 + (tid & 31);
        float acc = b_out[nn];
        const float* hr = g_h + (size_t)m * Hh;
#pragma unroll 8
        for (int k = 0; k < Hh; k++) acc += hr[k] * W_out[k * Oo + nn];
        out[m * Oo + nn] = acc;
    }
}

extern "C" void kernel_launch(void* const* d_in, const int* in_sizes, int n_in,
                              void* d_out, int out_size) {
    const float* x     = (const float*)d_in[0];
    const float* ts    = (const float*)d_in[1];
    const float* Wb0   = (const float*)d_in[2];
    const float* bb0   = (const float*)d_in[3];
    const float* Wbs   = (const float*)d_in[4];
    const float* bbs   = (const float*)d_in[5];
    const float* W_ff1 = (const float*)d_in[6];
    const float* b_ff1 = (const float*)d_in[7];
    const float* W_ff2 = (const float*)d_in[8];
    const float* b_ff2 = (const float*)d_in[9];
    const float* W_ta  = (const float*)d_in[10];
    const float* b_ta  = (const float*)d_in[11];
    const float* W_tb  = (const float*)d_in[12];
    const float* b_tb  = (const float*)d_in[13];
    const float* W_out = (const float*)d_in[14];
    const float* b_out = (const float*)d_in[15];

    cudaFuncSetAttribute(lnn_kernel, cudaFuncAttributeMaxDynamicSharedMemorySize, SMEM_BYTES);
    lnn_kernel<<<NCTA, NTHR, SMEM_BYTES>>>(x, ts, Wb0, bb0, Wbs, bbs,
                                           W_ff1, b_ff1, W_ff2, b_ff2,
                                           W_ta, b_ta, W_tb, b_tb,
                                           W_out, b_out, (float*)d_out);
}